// round 17
// baseline (speedup 1.0000x reference)
#include <cuda_runtime.h>
#include <cuda_fp16.h>
#include <math.h>
#include <float.h>

// Problem constants
#define B_   8
#define L_   2048
#define LOG2L 11
#define D_   512
#define DM_  512
#define KTOP 15

// ---------------- device scratch (static allocation only) ----------------
__device__ float g_qT[B_ * D_ * L_];   // (B, D, L)
__device__ float g_kT[B_ * D_ * L_];
__device__ float g_vT[B_ * D_ * L_];
__device__ float g_AT[B_ * D_ * L_];
__device__ float2 g_tw[L_ / 2];        // exp(-2*pi*i*j/L)

// ---------------- twiddle init ----------------
__global__ void twiddle_init_kernel() {
    int j = blockIdx.x * blockDim.x + threadIdx.x;
    if (j < L_ / 2) {
        float sn, cs;
        sincospif((float)j / 1024.0f, &sn, &cs);
        g_tw[j] = make_float2(cs, -sn);
    }
}

// ---------------- FP16 split helpers ----------------
__device__ __forceinline__ unsigned pack_hi(float a, float b) {
    __half2 h = __halves2half2(__float2half_rn(a), __float2half_rn(b));
    return *(unsigned*)&h;
}
__device__ __forceinline__ unsigned pack_lo(float a, float b) {
    float ra = a - __half2float(__float2half_rn(a));
    float rb = b - __half2float(__float2half_rn(b));
    __half2 h = __halves2half2(__float2half_rn(ra), __float2half_rn(rb));
    return *(unsigned*)&h;
}

__device__ __forceinline__ void mma_f16(float c[4], const unsigned a[4], const unsigned b[2]) {
    asm volatile(
        "mma.sync.aligned.m16n8k16.row.col.f32.f16.f16.f32 "
        "{%0,%1,%2,%3}, {%4,%5,%6,%7}, {%8,%9}, {%0,%1,%2,%3};\n"
        : "+f"(c[0]), "+f"(c[1]), "+f"(c[2]), "+f"(c[3])
        : "r"(a[0]), "r"(a[1]), "r"(a[2]), "r"(a[3]), "r"(b[0]), "r"(b[1]));
}

// ---------------- Fused 3-GEMM (fp16 split x3 products, fp32 accum) ----------------
// EXACT r5 champion version — FROZEN.
__global__ __launch_bounds__(256, 2)
void gemm3_fp16_kernel(const float* __restrict__ Qi, const float* __restrict__ Ki,
                       const float* __restrict__ Vi,
                       const float* __restrict__ WQ, const float* __restrict__ WK,
                       const float* __restrict__ WV,
                       const float* __restrict__ bQ, const float* __restrict__ bK,
                       const float* __restrict__ bV) {
    const int z = blockIdx.z;
    const float* X    = (z == 0) ? Qi : ((z == 1) ? Ki : Vi);
    const float* W    = (z == 0) ? WQ : ((z == 1) ? WK : WV);
    const float* bias = (z == 0) ? bQ : ((z == 1) ? bK : bV);
    float* outT       = (z == 0) ? g_qT : ((z == 1) ? g_kT : g_vT);

    __shared__ unsigned As2h[128][9], As2l[128][9];
    __shared__ unsigned Bs2h[8][132], Bs2l[8][132];

    const int tid = threadIdx.x;
    const int lane = tid & 31;
    const int w = tid >> 5;
    const int wm0 = (w & 1) * 64;
    const int wn0 = (w >> 1) * 32;
    const int g = lane >> 2;
    const int c = lane & 3;
    const int m0 = blockIdx.x * 128;
    const int n0 = blockIdx.y * 128;

    const int rowA = tid >> 2;
    const int kqA  = (tid & 3) << 2;
    const int pB   = tid >> 5;
    const int nqB  = (lane) << 2;
    const float* pA0 = &X[(size_t)(m0 + rowA) * DM_ + kqA];
    const float* pA1 = pA0 + (size_t)64 * DM_;
    const float* pB0 = &W[(size_t)(2 * pB) * D_ + n0 + nqB];
    const float* pB1 = pB0 + D_;

    float cacc[4][4][4];
#pragma unroll
    for (int mt = 0; mt < 4; mt++)
#pragma unroll
        for (int nt = 0; nt < 4; nt++)
#pragma unroll
            for (int i = 0; i < 4; i++) cacc[mt][nt][i] = 0.0f;

    float4 av0 = *(const float4*)pA0;
    float4 av1 = *(const float4*)pA1;
    float4 bv0 = *(const float4*)pB0;
    float4 bv1 = *(const float4*)pB1;

#pragma unroll 1
    for (int k0 = 0; k0 < DM_; k0 += 16) {
        const int kp = kqA >> 1;
        As2h[rowA][kp]          = pack_hi(av0.x, av0.y);
        As2h[rowA][kp + 1]      = pack_hi(av0.z, av0.w);
        As2l[rowA][kp]          = pack_lo(av0.x, av0.y);
        As2l[rowA][kp + 1]      = pack_lo(av0.z, av0.w);
        As2h[rowA + 64][kp]     = pack_hi(av1.x, av1.y);
        As2h[rowA + 64][kp + 1] = pack_hi(av1.z, av1.w);
        As2l[rowA + 64][kp]     = pack_lo(av1.x, av1.y);
        As2l[rowA + 64][kp + 1] = pack_lo(av1.z, av1.w);
        {
            uint4 uh = make_uint4(pack_hi(bv0.x, bv1.x), pack_hi(bv0.y, bv1.y),
                                  pack_hi(bv0.z, bv1.z), pack_hi(bv0.w, bv1.w));
            uint4 ul = make_uint4(pack_lo(bv0.x, bv1.x), pack_lo(bv0.y, bv1.y),
                                  pack_lo(bv0.z, bv1.z), pack_lo(bv0.w, bv1.w));
            *(uint4*)&Bs2h[pB][nqB] = uh;
            *(uint4*)&Bs2l[pB][nqB] = ul;
        }
        __syncthreads();

        if (k0 + 16 < DM_) {
            av0 = *(const float4*)(pA0 + k0 + 16);
            av1 = *(const float4*)(pA1 + k0 + 16);
            bv0 = *(const float4*)(pB0 + (size_t)(k0 + 16) * D_);
            bv1 = *(const float4*)(pB1 + (size_t)(k0 + 16) * D_);
        }

        unsigned bh[4][2], bl[4][2];
#pragma unroll
        for (int nt = 0; nt < 4; nt++) {
            int cn = wn0 + nt * 8 + g;
            bh[nt][0] = Bs2h[c][cn];
            bh[nt][1] = Bs2h[c + 4][cn];
            bl[nt][0] = Bs2l[c][cn];
            bl[nt][1] = Bs2l[c + 4][cn];
        }
#pragma unroll
        for (int mt = 0; mt < 4; mt++) {
            int row = wm0 + mt * 16 + g;
            unsigned ah[4], al[4];
            ah[0] = As2h[row][c];
            ah[1] = As2h[row + 8][c];
            ah[2] = As2h[row][c + 4];
            ah[3] = As2h[row + 8][c + 4];
            al[0] = As2l[row][c];
            al[1] = As2l[row + 8][c];
            al[2] = As2l[row][c + 4];
            al[3] = As2l[row + 8][c + 4];
#pragma unroll
            for (int nt = 0; nt < 4; nt++) {
                mma_f16(cacc[mt][nt], ah, bl[nt]);
                mma_f16(cacc[mt][nt], al, bh[nt]);
                mma_f16(cacc[mt][nt], ah, bh[nt]);
            }
        }
        __syncthreads();
    }

    const int b = m0 >> LOG2L;
    const int tbase = (m0 & (L_ - 1)) + wm0 + g;
#pragma unroll
    for (int nt = 0; nt < 4; nt++) {
        const int d0 = n0 + wn0 + nt * 8 + 2 * c;
        const float bi0 = bias[d0];
        const float bi1 = bias[d0 + 1];
        const size_t row0 = ((size_t)(b * D_ + d0) << LOG2L);
        const size_t row1 = row0 + L_;
#pragma unroll
        for (int mt = 0; mt < 4; mt++) {
            const int t = tbase + mt * 16;
            outT[row0 + t]     = cacc[mt][nt][0] + bi0;
            outT[row1 + t]     = cacc[mt][nt][1] + bi1;
            outT[row0 + t + 8] = cacc[mt][nt][2] + bi0;
            outT[row1 + t + 8] = cacc[mt][nt][3] + bi1;
        }
    }
}

// ---------------- complex helpers ----------------
__device__ __forceinline__ float2 cmul(float2 a, float2 b) {
    return make_float2(a.x * b.x - a.y * b.y, a.x * b.y + a.y * b.x);
}
__device__ __forceinline__ float2 cmulc(float2 a, float2 b) {   // a * conj(b)
    return make_float2(a.x * b.x + a.y * b.y, a.y * b.x - a.x * b.y);
}
__device__ __forceinline__ float2 cadd(float2 a, float2 b) { return make_float2(a.x + b.x, a.y + b.y); }
__device__ __forceinline__ float2 csub(float2 a, float2 b) { return make_float2(a.x - b.x, a.y - b.y); }

#define ZI(i) ((i) + ((i) >> 5))
#define XI(i) ((i) + ((i) >> 5))

#define BF_F(A, B, W) do { float2 _t = csub(A, B); A = cadd(A, B); B = cmul(_t, W); } while (0)
#define BF_I(A, B, W) do { float2 _bw = cmulc(B, W); B = csub(A, _bw); A = cadd(A, _bw); } while (0)

__device__ __forceinline__ float2 xspec(float2 Zf, float2 Zm, float scl) {
    float2 u = make_float2(Zf.x + Zm.x, Zf.y - Zm.y);
    float2 v = make_float2(Zf.x - Zm.x, -Zf.y - Zm.y);
    float2 pr = cmul(u, v);
    return make_float2(-pr.y * scl, pr.x * scl);
}

// ---------------- fused FFT-correlation + top-k + softmax + gather ----------------
// 256 threads = 2 columns/CTA (threads 0-127 col A, 128-255 col B).
// Per column: single 2112-float2 buffer (in-place fwd FFT + in-place xspec;
// X[0..1055) and vcol[1056..2080) overlay it afterward).
__global__ __launch_bounds__(256)
void corr_attn_kernel() {
    __shared__ float2 tw[L_ / 2];              // 8 KB, shared by both columns
    __shared__ float2 buf[2][L_ + L_ / 32];    // 2 x 16.5 KB
    __shared__ float  red_v[2][8];
    __shared__ int    red_i[2][8];

    const int tid = threadIdx.x;
    const int t = tid & 127;                   // thread-in-column
    const int hw = tid >> 7;                   // column half 0/1
    const int lane = tid & 31;
    const int w4 = t >> 5;                     // warp within column (0..3)
    const size_t col = ((size_t)(2 * blockIdx.x + hw)) << LOG2L;

    float2* bf = buf[hw];
    float2* zx = bf;                           // X overlays buffer base (XI idx)
    float*  vcol = (float*)(bf + 1056);        // 2048 floats at float2[1056..2080)

    for (int i = tid; i < L_ / 2; i += 256) tw[i] = g_tw[i];

    float2 zr[16];
#pragma unroll
    for (int q = 0; q < 16; q++)
        zr[q] = make_float2(g_qT[col + t + 128 * q], g_kT[col + t + 128 * q]);
    __syncthreads();   // twiddles ready

    // ======== forward DIF, group 1: spans 1024/512/256/128 ========
#pragma unroll
    for (int q = 0; q < 8; q++) {
        float2 wv = tw[t + 128 * q];
        BF_F(zr[q], zr[q + 8], wv);
    }
#pragma unroll
    for (int h = 0; h < 16; h += 8)
#pragma unroll
        for (int q = 0; q < 4; q++) {
            float2 wv = tw[(t + 128 * q) << 1];
            BF_F(zr[h + q], zr[h + q + 4], wv);
        }
#pragma unroll
    for (int h = 0; h < 16; h += 4)
#pragma unroll
        for (int q = 0; q < 2; q++) {
            float2 wv = tw[(t + 128 * q) << 2];
            BF_F(zr[h + q], zr[h + q + 2], wv);
        }
    {
        float2 wv = tw[t << 3];
#pragma unroll
        for (int p = 0; p < 16; p += 2) BF_F(zr[p], zr[p + 1], wv);
    }
#pragma unroll
    for (int q = 0; q < 16; q++) bf[ZI(t + 128 * q)] = zr[q];
    __syncthreads();

    // ======== group 2: spans 64/32/16/8 (stride-8 ownership, in-place) ========
    const int c8 = (t & 7) + (t >> 3) * 128;
#pragma unroll
    for (int q = 0; q < 16; q++) zr[q] = bf[ZI(c8 + 8 * q)];
#pragma unroll
    for (int q = 0; q < 8; q++) {
        float2 wv = tw[((t & 7) + 8 * q) << 4];
        BF_F(zr[q], zr[q + 8], wv);
    }
#pragma unroll
    for (int h = 0; h < 16; h += 8)
#pragma unroll
        for (int q = 0; q < 4; q++) {
            float2 wv = tw[((t & 7) + 8 * q) << 5];
            BF_F(zr[h + q], zr[h + q + 4], wv);
        }
#pragma unroll
    for (int h = 0; h < 16; h += 4)
#pragma unroll
        for (int q = 0; q < 2; q++) {
            float2 wv = tw[((t & 7) + 8 * q) << 6];
            BF_F(zr[h + q], zr[h + q + 2], wv);
        }
    {
        float2 wv = tw[(t & 7) << 7];
#pragma unroll
        for (int p = 0; p < 16; p += 2) BF_F(zr[p], zr[p + 1], wv);
    }
#pragma unroll
    for (int q = 0; q < 16; q++) bf[ZI(c8 + 8 * q)] = zr[q];
    __syncthreads();

    // ======== group 3: spans 4/2/1 (contiguous, in-place) ========
    const int base16 = t * 16;
#pragma unroll
    for (int q = 0; q < 16; q++) zr[q] = bf[ZI(base16 + q)];
#pragma unroll
    for (int h = 0; h < 16; h += 8)
#pragma unroll
        for (int q = 0; q < 4; q++) {
            float2 wv = tw[q << 8];
            BF_F(zr[h + q], zr[h + q + 4], wv);
        }
#pragma unroll
    for (int h = 0; h < 16; h += 4)
#pragma unroll
        for (int q = 0; q < 2; q++) {
            float2 wv = tw[q << 9];
            BF_F(zr[h + q], zr[h + q + 2], wv);
        }
#pragma unroll
    for (int p = 0; p < 16; p += 2) {
        float2 a = zr[p], b = zr[p + 1];
        zr[p] = cadd(a, b);
        zr[p + 1] = csub(a, b);
    }
#pragma unroll
    for (int q = 0; q < 16; q++) bf[ZI(base16 + q)] = zr[q];
    __syncthreads();
    // bf = Z in bit-reversed-11 order

    // ======== cross-spectrum IN-PLACE (pair ownership: f with L-f) ========
    const float scl = 0.25f / (float)L_;
#pragma unroll
    for (int it = 0; it < 8; it++) {
        int f = t + 128 * it;                    // 0..1023
        int fm = (L_ - f) & (L_ - 1);
        int p  = __brev((unsigned)f) >> 21;
        int pm = __brev((unsigned)fm) >> 21;
        float2 Zf = bf[ZI(p)], Zm = bf[ZI(pm)];
        float2 Sf = xspec(Zf, Zm, scl);
        float2 Sm = xspec(Zm, Zf, scl);
        bf[ZI(p)] = Sf;
        bf[ZI(pm)] = Sm;
        if (f == 0) {                            // Nyquist (pos 1) self-pair
            float2 Zn = bf[ZI(1)];
            bf[ZI(1)] = xspec(Zn, Zn, scl);
        }
    }
    __syncthreads();

    // ======== fused combine + inverse group A (reads all S, then overlays) ====
    float2 X[8];
    {
        float2 Sp[16];
#pragma unroll
        for (int e = 0; e < 16; e++) Sp[e] = bf[ZI(base16 + e)];
#pragma unroll
        for (int cc = 0; cc < 8; cc++) {
            int j = 8 * t + cc;
            int k = __brev((unsigned)j) >> 22;   // brev10
            float2 E = cadd(Sp[2 * cc], Sp[2 * cc + 1]);
            float2 Dd = csub(Sp[2 * cc], Sp[2 * cc + 1]);
            float2 O = cmulc(Dd, tw[k]);
            X[cc] = make_float2(E.x - O.y, E.y + O.x);   // E + i*O
        }
#pragma unroll
        for (int p = 0; p < 8; p += 2) {
            float2 a = X[p], b = X[p + 1];
            X[p] = cadd(a, b);
            X[p + 1] = csub(a, b);
        }
#pragma unroll
        for (int h = 0; h < 8; h += 4)
#pragma unroll
            for (int q = 0; q < 2; q++) {
                float2 wv = tw[q << 9];
                BF_I(X[h + q], X[h + q + 2], wv);
            }
    }
    __syncthreads();   // ALL S reads complete -> buffer reusable for X + vcol
#pragma unroll
    for (int cc = 0; cc < 8; cc++) zx[XI(8 * t + cc)] = X[cc];

    for (int i = t; i < L_; i += 128) vcol[i] = g_vT[col + i];
    __syncthreads();

    // ======== inverse group B: spans 4/8/16 ========
    {
        const int c4b = (t & 3) + (t >> 2) * 32;
        float2 xr[8];
#pragma unroll
        for (int q = 0; q < 8; q++) xr[q] = zx[XI(c4b + 4 * q)];
        {
            float2 wv = tw[(t & 3) << 8];
#pragma unroll
            for (int p = 0; p < 8; p += 2) BF_I(xr[p], xr[p + 1], wv);
        }
#pragma unroll
        for (int h = 0; h < 8; h += 4)
#pragma unroll
            for (int q = 0; q < 2; q++) {
                float2 wv = tw[((t & 3) + 4 * q) << 7];
                BF_I(xr[h + q], xr[h + q + 2], wv);
            }
#pragma unroll
        for (int q = 0; q < 4; q++) {
            float2 wv = tw[((t & 3) + 4 * q) << 6];
            BF_I(xr[q], xr[q + 4], wv);
        }
#pragma unroll
        for (int q = 0; q < 8; q++) zx[XI(c4b + 4 * q)] = xr[q];
    }
    __syncthreads();

    // ======== inverse group C: spans 32/64/128 ========
    {
        const int c32b = (t & 31) + (t >> 5) * 256;
        float2 xr[8];
#pragma unroll
        for (int q = 0; q < 8; q++) xr[q] = zx[XI(c32b + 32 * q)];
        {
            float2 wv = tw[(t & 31) << 5];
#pragma unroll
            for (int p = 0; p < 8; p += 2) BF_I(xr[p], xr[p + 1], wv);
        }
#pragma unroll
        for (int h = 0; h < 8; h += 4)
#pragma unroll
            for (int q = 0; q < 2; q++) {
                float2 wv = tw[((t & 31) + 32 * q) << 4];
                BF_I(xr[h + q], xr[h + q + 2], wv);
            }
#pragma unroll
        for (int q = 0; q < 4; q++) {
            float2 wv = tw[((t & 31) + 32 * q) << 3];
            BF_I(xr[q], xr[q + 4], wv);
        }
#pragma unroll
        for (int q = 0; q < 8; q++) zx[XI(c32b + 32 * q)] = xr[q];
    }
    __syncthreads();

    // ======== inverse group D: spans 256/512 (registers; feeds top-k) ========
    float2 xr[8];
#pragma unroll
    for (int q = 0; q < 8; q++) xr[q] = zx[XI(t + 128 * q)];
#pragma unroll
    for (int h = 0; h < 8; h += 4)
#pragma unroll
        for (int q = 0; q < 2; q++) {
            float2 wv = tw[(t + 128 * q) << 2];
            BF_I(xr[h + q], xr[h + q + 2], wv);
        }
#pragma unroll
    for (int q = 0; q < 4; q++) {
        float2 wv = tw[(t + 128 * q) << 1];
        BF_I(xr[q], xr[q + 4], wv);
    }
    // xr[q] = x[t + 128q]; R[2m] = x.x, R[2m+1] = x.y

    // ---- top-15 per column; idx = 2*t + 256*q + comp ----
    float rv[16];
#pragma unroll
    for (int q = 0; q < 8; q++) { rv[2 * q] = xr[q].x; rv[2 * q + 1] = xr[q].y; }

    float wsel[KTOP];
    int isel[KTOP];
#pragma unroll 1
    for (int rnd = 0; rnd < KTOP; rnd++) {
        float best = rv[0];
        int bq = 0;
#pragma unroll
        for (int q = 1; q < 16; q++)
            if (rv[q] > best) { best = rv[q]; bq = q; }
        int bi = 2 * t + 256 * (bq >> 1) + (bq & 1);
#pragma unroll
        for (int off = 16; off > 0; off >>= 1) {
            float ov = __shfl_xor_sync(0xffffffffu, best, off);
            int oi = __shfl_xor_sync(0xffffffffu, bi, off);
            if (ov > best || (ov == best && oi < bi)) { best = ov; bi = oi; }
        }
        const int slot = (rnd & 1) * 4;
        if (lane == 0) { red_v[hw][slot + w4] = best; red_i[hw][slot + w4] = bi; }
        __syncthreads();
        float gb = red_v[hw][slot];
        int gi = red_i[hw][slot];
#pragma unroll
        for (int ww = 1; ww < 4; ww++) {
            float ov = red_v[hw][slot + ww];
            int oi = red_i[hw][slot + ww];
            if (ov > gb || (ov == gb && oi < gi)) { gb = ov; gi = oi; }
        }
        wsel[rnd] = gb;
        isel[rnd] = gi;
#pragma unroll
        for (int q = 0; q < 8; q++) {
            if (gi == 2 * t + 256 * q)     rv[2 * q]     = -FLT_MAX;
            if (gi == 2 * t + 256 * q + 1) rv[2 * q + 1] = -FLT_MAX;
        }
    }

    // ---- softmax (redundant per thread) ----
    float m = wsel[0];
#pragma unroll
    for (int k = 1; k < KTOP; k++) m = fmaxf(m, wsel[k]);
    float sum = 0.0f;
    float wnorm[KTOP];
#pragma unroll
    for (int k = 0; k < KTOP; k++) { float e = __expf(wsel[k] - m); wnorm[k] = e; sum += e; }
    const float inv = 1.0f / sum;
#pragma unroll
    for (int k = 0; k < KTOP; k++) wnorm[k] *= inv;

    // ---- gather ----
    for (int l = t; l < L_; l += 128) {
        float acc = 0.0f;
#pragma unroll
        for (int k = 0; k < KTOP; k++)
            acc = fmaf(wnorm[k], vcol[(l + isel[k]) & (L_ - 1)], acc);
        g_AT[col + l] = acc;
    }
}

// ---------------- transpose (B, D, L) -> (B, L, D) ----------------
__global__ void transpose_kernel(float* __restrict__ A) {
    __shared__ float tile[32][33];
    const int b = blockIdx.z;
    const int l0 = blockIdx.x * 32;
    const int d0 = blockIdx.y * 32;
    const int tx = threadIdx.x, ty = threadIdx.y;
#pragma unroll
    for (int r = 0; r < 32; r += 8)
        tile[ty + r][tx] = g_AT[((size_t)(b * D_ + d0 + ty + r) << LOG2L) + l0 + tx];
    __syncthreads();
#pragma unroll
    for (int r = 0; r < 32; r += 8)
        A[((size_t)(b * L_ + l0 + ty + r)) * D_ + d0 + tx] = tile[tx][ty + r];
}

// ---------------- launch ----------------
extern "C" void kernel_launch(void* const* d_in, const int* in_sizes, int n_in,
                              void* d_out, int out_size) {
    const float* Q   = (const float*)d_in[0];
    const float* K   = (const float*)d_in[1];
    const float* V   = (const float*)d_in[2];
    const float* WQw = (const float*)d_in[3];
    const float* WQb = (const float*)d_in[4];
    const float* WKw = (const float*)d_in[5];
    const float* WKb = (const float*)d_in[6];
    const float* WVw = (const float*)d_in[7];
    const float* WVb = (const float*)d_in[8];
    float* out = (float*)d_out;

    cudaFuncSetAttribute(corr_attn_kernel,
                         cudaFuncAttributePreferredSharedMemoryCarveout, 100);

    twiddle_init_kernel<<<4, 256>>>();

    dim3 ggrid(B_ * L_ / 128, D_ / 128, 3);   // (128, 4, 3)
    gemm3_fp16_kernel<<<ggrid, 256>>>(Q, K, V, WQw, WKw, WVw, WQb, WKb, WVb);

    corr_attn_kernel<<<B_ * D_ / 2, 256>>>();

    dim3 tgrid(L_ / 32, D_ / 32, B_);         // (64, 16, 8)
    transpose_kernel<<<tgrid, dim3(32, 8)>>>(out);
}